// round 3
// baseline (speedup 1.0000x reference)
#include <cuda_runtime.h>
#include <cuda_bf16.h>
#include <stdint.h>

#define N_NODES 50000
#define N_EDGES 800000
#define N_GRAPHS 256
#define DIN0 32
#define HID 96
#define N_TARG 8
#define BN_EPS 1e-5f

// ---------------- device scratch (static, allowed) ----------------
__device__ float g_h[(size_t)N_NODES * HID];     // layer outputs
__device__ float g_agg[(size_t)N_NODES * HID];   // aggregation buffer (self + neighbors)
__device__ float g_z[(size_t)N_NODES * HID];     // intermediate z
__device__ float g_pool[N_GRAPHS * HID];         // pooled

// ---------------- small kernels ----------------
__global__ void zero_pool_kernel() {
    int i = blockIdx.x * blockDim.x + threadIdx.x;
    if (i < N_GRAPHS * HID) g_pool[i] = 0.f;
}

// copy x (N x 32) into agg buffer (self term for layer 1)
__global__ void copy_x_kernel(const float* __restrict__ x) {
    int i = blockIdx.x * blockDim.x + threadIdx.x;
    int total = N_NODES * DIN0 / 4;
    if (i < total) {
        ((float4*)g_agg)[i] = ((const float4*)x)[i];
    }
}

// edge scatter: agg[dst] += h[src], DIN features per edge, float4 lanes
template<int DIN>
__global__ void edge_kernel(const float* __restrict__ h,
                            const int* __restrict__ ei,
                            float* __restrict__ agg) {
    const int VPR = DIN / 4;
    int t = blockIdx.x * blockDim.x + threadIdx.x;
    int e = t / VPR;
    int lane = t - e * VPR;
    if (e >= N_EDGES) return;
    int s = __ldg(&ei[e]);
    int d = __ldg(&ei[N_EDGES + e]);
    float4 v = *(const float4*)(h + (size_t)s * DIN + lane * 4);
    float* dst = agg + (size_t)d * DIN + lane * 4;
    atomicAdd(dst + 0, v.x);
    atomicAdd(dst + 1, v.y);
    atomicAdd(dst + 2, v.z);
    atomicAdd(dst + 3, v.w);
}

// ---------------- GEMM: out = epilogue(A[N x DIN] @ W[DIN x 96]) ----------------
// BM=128 rows/block, 256 threads, thread microtile 8 rows x 6 cols.
// W fully in smem; A k-tiled (KT=16) in smem. Static smem = DIN*96*4 + 128*17*4 <= 45.6KB.
template<int DIN, bool HAS_BN, bool DUAL>
__global__ void __launch_bounds__(256, 1) gemm_kernel(
    const float* __restrict__ A, const float* __restrict__ W,
    const float* __restrict__ bias,
    const float* __restrict__ gamma, const float* __restrict__ beta,
    const float* __restrict__ rmean, const float* __restrict__ rvar,
    float* __restrict__ out, float* __restrict__ out2)
{
    constexpr int H = HID;
    constexpr int BM = 128;
    constexpr int KT = 16;
    constexpr int NKT = DIN / KT;
    __shared__ float Ws[DIN * H];
    __shared__ float As[BM * (KT + 1)];

    const int tid = threadIdx.x;
    const int row0 = blockIdx.x * BM;

    // load W (row-major, same layout as input)
    for (int i = tid; i < DIN * H; i += 256) Ws[i] = W[i];

    const int row_t = tid & 15;        // 16 row-threads, rows row_t + 16*i
    const int col_t = tid >> 4;        // 16 col-threads, 6 cols each
    const int c0 = col_t * 6;

    float acc[8][6];
    #pragma unroll
    for (int i = 0; i < 8; i++)
        #pragma unroll
        for (int j = 0; j < 6; j++) acc[i][j] = 0.f;

    for (int kt = 0; kt < NKT; kt++) {
        // stage A k-tile: As[r][kk], padded lda = KT+1
        for (int i = tid; i < BM * KT; i += 256) {
            int r = i >> 4;          // i / KT
            int kk = i & 15;         // i % KT
            int gr = row0 + r;
            As[r * (KT + 1) + kk] =
                (gr < N_NODES) ? A[(size_t)gr * DIN + kt * KT + kk] : 0.f;
        }
        __syncthreads();
        #pragma unroll
        for (int kk = 0; kk < KT; kk++) {
            int k = kt * KT + kk;
            float w[6];
            #pragma unroll
            for (int j = 0; j < 6; j++) w[j] = Ws[k * H + c0 + j];
            #pragma unroll
            for (int i = 0; i < 8; i++) {
                float a = As[(row_t + 16 * i) * (KT + 1) + kk];
                #pragma unroll
                for (int j = 0; j < 6; j++) acc[i][j] = fmaf(a, w[j], acc[i][j]);
            }
        }
        __syncthreads();
    }

    // epilogue: (+bias), optional BN, relu
    float sc[6], sh[6];
    #pragma unroll
    for (int j = 0; j < 6; j++) {
        int c = c0 + j;
        if (HAS_BN) {
            float s = gamma[c] * rsqrtf(rvar[c] + BN_EPS);
            sc[j] = s;
            sh[j] = (bias[c] - rmean[c]) * s + beta[c];
        } else {
            sc[j] = 1.f;
            sh[j] = bias[c];
        }
    }
    #pragma unroll
    for (int i = 0; i < 8; i++) {
        int gr = row0 + row_t + 16 * i;
        if (gr < N_NODES) {
            #pragma unroll
            for (int j = 0; j < 6; j++) {
                float v = fmaf(acc[i][j], sc[j], sh[j]);
                v = fmaxf(v, 0.f);
                out[(size_t)gr * H + c0 + j] = v;
                if (DUAL) out2[(size_t)gr * H + c0 + j] = v;
            }
        }
    }
}

// ---------------- pooling + head ----------------
__global__ void pool_kernel(const int* __restrict__ batch) {
    int t = blockIdx.x * blockDim.x + threadIdx.x;
    const int VPR = HID / 4; // 24
    int n = t / VPR;
    int lane = t - n * VPR;
    if (n >= N_NODES) return;
    int b = __ldg(&batch[n]);
    float4 v = *(const float4*)(g_h + (size_t)n * HID + lane * 4);
    float* dst = g_pool + (size_t)b * HID + lane * 4;
    atomicAdd(dst + 0, v.x);
    atomicAdd(dst + 1, v.y);
    atomicAdd(dst + 2, v.z);
    atomicAdd(dst + 3, v.w);
}

__global__ void head_kernel(const int* __restrict__ r_target,
                            const float* __restrict__ head_w,
                            const float* __restrict__ head_b,
                            float* __restrict__ out) {
    int b = threadIdx.x;
    if (b >= N_GRAPHS) return;
    int t = r_target[b];
    const float* w = head_w + (size_t)t * HID;
    const float* p = g_pool + (size_t)b * HID;
    float acc = 0.f;
    #pragma unroll
    for (int k = 0; k < HID; k++) acc = fmaf(p[k], w[k], acc);
    out[b] = acc + head_b[t];
}

// ---------------- launch ----------------
extern "C" void kernel_launch(void* const* d_in, const int* in_sizes, int n_in,
                              void* d_out, int out_size) {
    const float* x    = (const float*)d_in[0];
    const int*   ei   = (const int*)d_in[1];
    const int*   bat  = (const int*)d_in[2];
    const int*   rtg  = (const int*)d_in[3];

    const float* w_in[3]  = {(const float*)d_in[4],  (const float*)d_in[12], (const float*)d_in[20]};
    const float* b_in[3]  = {(const float*)d_in[5],  (const float*)d_in[13], (const float*)d_in[21]};
    const float* gam[3]   = {(const float*)d_in[6],  (const float*)d_in[14], (const float*)d_in[22]};
    const float* bet[3]   = {(const float*)d_in[7],  (const float*)d_in[15], (const float*)d_in[23]};
    const float* rme[3]   = {(const float*)d_in[8],  (const float*)d_in[16], (const float*)d_in[24]};
    const float* rva[3]   = {(const float*)d_in[9],  (const float*)d_in[17], (const float*)d_in[25]};
    const float* w_out[3] = {(const float*)d_in[10], (const float*)d_in[18], (const float*)d_in[26]};
    const float* b_out[3] = {(const float*)d_in[11], (const float*)d_in[19], (const float*)d_in[27]};
    const float* head_w   = (const float*)d_in[28];
    const float* head_b   = (const float*)d_in[29];
    float* out = (float*)d_out;

    float *hbuf, *aggbuf, *zbuf;
    cudaGetSymbolAddress((void**)&hbuf, g_h);
    cudaGetSymbolAddress((void**)&aggbuf, g_agg);
    cudaGetSymbolAddress((void**)&zbuf, g_z);

    const int TB = 256;
    const int gemm_blocks = (N_NODES + 127) / 128;

    // pool accumulator init (needed before pool_kernel; scheduled first)
    zero_pool_kernel<<<(N_GRAPHS * HID + TB - 1) / TB, TB>>>();

    // ---- layer 1 (Din=32) ----
    copy_x_kernel<<<(N_NODES * DIN0 / 4 + TB - 1) / TB, TB>>>(x);
    {
        int tot = N_EDGES * (DIN0 / 4);
        edge_kernel<DIN0><<<(tot + TB - 1) / TB, TB>>>(x, ei, aggbuf);
    }
    gemm_kernel<DIN0, true, false><<<gemm_blocks, TB>>>(
        aggbuf, w_in[0], b_in[0], gam[0], bet[0], rme[0], rva[0], zbuf, nullptr);
    gemm_kernel<HID, false, true><<<gemm_blocks, TB>>>(
        zbuf, w_out[0], b_out[0], nullptr, nullptr, nullptr, nullptr, hbuf, aggbuf);

    // ---- layer 2 ----
    {
        int tot = N_EDGES * (HID / 4);
        edge_kernel<HID><<<(tot + TB - 1) / TB, TB>>>(hbuf, ei, aggbuf);
    }
    gemm_kernel<HID, true, false><<<gemm_blocks, TB>>>(
        aggbuf, w_in[1], b_in[1], gam[1], bet[1], rme[1], rva[1], zbuf, nullptr);
    gemm_kernel<HID, false, true><<<gemm_blocks, TB>>>(
        zbuf, w_out[1], b_out[1], nullptr, nullptr, nullptr, nullptr, hbuf, aggbuf);

    // ---- layer 3 ----
    {
        int tot = N_EDGES * (HID / 4);
        edge_kernel<HID><<<(tot + TB - 1) / TB, TB>>>(hbuf, ei, aggbuf);
    }
    gemm_kernel<HID, true, false><<<gemm_blocks, TB>>>(
        aggbuf, w_in[2], b_in[2], gam[2], bet[2], rme[2], rva[2], zbuf, nullptr);
    gemm_kernel<HID, false, false><<<gemm_blocks, TB>>>(
        zbuf, w_out[2], b_out[2], nullptr, nullptr, nullptr, nullptr, hbuf, nullptr);

    // ---- pooling + head ----
    {
        int tot = N_NODES * (HID / 4);
        pool_kernel<<<(tot + TB - 1) / TB, TB>>>(bat);
    }
    head_kernel<<<1, 256>>>(rtg, head_w, head_b, out);
}

// round 4
// speedup vs baseline: 1.6440x; 1.6440x over previous
#include <cuda_runtime.h>
#include <cuda_bf16.h>
#include <stdint.h>

#define N_NODES 50000
#define N_EDGES 800000
#define N_GRAPHS 256
#define DIN0 32
#define HID 96
#define BN_EPS 1e-5f

// ---------------- device scratch (static, allowed) ----------------
__device__ float g_h[(size_t)N_NODES * HID];     // layer outputs
__device__ float g_agg[(size_t)N_NODES * HID];   // aggregation buffer (self + neighbors)
__device__ float g_z[(size_t)N_NODES * HID];     // intermediate z
__device__ float g_pool[N_GRAPHS * HID];         // pooled

// vectorized fire-and-forget global reduction (sm_90+)
__device__ __forceinline__ void red_add_v4(float* addr, float4 v) {
    asm volatile("red.global.add.v4.f32 [%0], {%1, %2, %3, %4};"
                 :: "l"(addr), "f"(v.x), "f"(v.y), "f"(v.z), "f"(v.w)
                 : "memory");
}

// ---------------- small kernels ----------------
__global__ void zero_pool_kernel() {
    int i = blockIdx.x * blockDim.x + threadIdx.x;
    if (i < N_GRAPHS * HID) g_pool[i] = 0.f;
}

// copy x (N x 32) into agg buffer (self term for layer 1)
__global__ void copy_x_kernel(const float* __restrict__ x) {
    int i = blockIdx.x * blockDim.x + threadIdx.x;
    int total = N_NODES * DIN0 / 4;
    if (i < total) {
        ((float4*)g_agg)[i] = ((const float4*)x)[i];
    }
}

// edge scatter: agg[dst] += h[src], DIN features per edge, one red.v4 per lane
template<int DIN>
__global__ void edge_kernel(const float* __restrict__ h,
                            const int* __restrict__ ei,
                            float* __restrict__ agg) {
    const int VPR = DIN / 4;
    int t = blockIdx.x * blockDim.x + threadIdx.x;
    int e = t / VPR;
    int lane = t - e * VPR;
    if (e >= N_EDGES) return;
    int s = __ldg(&ei[e]);
    int d = __ldg(&ei[N_EDGES + e]);
    float4 v = *(const float4*)(h + (size_t)s * DIN + lane * 4);
    red_add_v4(agg + (size_t)d * DIN + lane * 4, v);
}

// ---------------- GEMM: out = epilogue(A[N x DIN] @ W[DIN x 96]) ----------------
// BM=64 rows/block, 256 threads, microtile 4 rows x 6 cols, 4 blocks/SM.
// W fully smem-resident; A k-tiled (KT=32, pad 33 -> conflict-free strided rows).
template<int DIN, bool HAS_BN, bool DUAL>
__global__ void __launch_bounds__(256, 4) gemm_kernel(
    const float* __restrict__ A, const float* __restrict__ W,
    const float* __restrict__ bias,
    const float* __restrict__ gamma, const float* __restrict__ beta,
    const float* __restrict__ rmean, const float* __restrict__ rvar,
    float* __restrict__ out, float* __restrict__ out2)
{
    constexpr int H = HID;
    constexpr int BM = 64;
    constexpr int KT = 32;
    constexpr int NKT = DIN / KT;
    __shared__ float Ws[DIN * H];            // <= 36 KB
    __shared__ float As[BM * (KT + 1)];      // 8.25 KB

    const int tid = threadIdx.x;
    const int row0 = blockIdx.x * BM;

    // load W via float4 (DIN*H multiple of 4, contiguous)
    for (int i = tid; i < DIN * H / 4; i += 256)
        ((float4*)Ws)[i] = ((const float4*)W)[i];

    const int row_t = tid & 15;        // 16 row-threads; rows row_t + 16*i
    const int col_t = tid >> 4;        // 16 col-threads, 6 cols each
    const int c0 = col_t * 6;

    float acc[4][6];
    #pragma unroll
    for (int i = 0; i < 4; i++)
        #pragma unroll
        for (int j = 0; j < 6; j++) acc[i][j] = 0.f;

    for (int kt = 0; kt < NKT; kt++) {
        // stage A k-tile via float4 loads: As[r][kk], pad stride KT+1
        #pragma unroll
        for (int i = tid; i < BM * KT / 4; i += 256) {
            int r  = i >> 3;           // KT/4 = 8 vectors per row
            int kv = i & 7;
            int gr = row0 + r;
            float4 v = make_float4(0.f, 0.f, 0.f, 0.f);
            if (gr < N_NODES)
                v = *(const float4*)(A + (size_t)gr * DIN + kt * KT + kv * 4);
            int base = r * (KT + 1) + kv * 4;
            As[base + 0] = v.x; As[base + 1] = v.y;
            As[base + 2] = v.z; As[base + 3] = v.w;
        }
        __syncthreads();
        #pragma unroll 8
        for (int kk = 0; kk < KT; kk++) {
            const float* wrow = Ws + (kt * KT + kk) * H + c0;
            float w[6];
            #pragma unroll
            for (int j = 0; j < 6; j++) w[j] = wrow[j];
            float a[4];
            #pragma unroll
            for (int i = 0; i < 4; i++) a[i] = As[(row_t + 16 * i) * (KT + 1) + kk];
            #pragma unroll
            for (int i = 0; i < 4; i++)
                #pragma unroll
                for (int j = 0; j < 6; j++) acc[i][j] = fmaf(a[i], w[j], acc[i][j]);
        }
        __syncthreads();
    }

    // epilogue: (+bias), optional BN, relu
    float sc[6], sh[6];
    #pragma unroll
    for (int j = 0; j < 6; j++) {
        int c = c0 + j;
        if (HAS_BN) {
            float s = gamma[c] * rsqrtf(rvar[c] + BN_EPS);
            sc[j] = s;
            sh[j] = (bias[c] - rmean[c]) * s + beta[c];
        } else {
            sc[j] = 1.f;
            sh[j] = bias[c];
        }
    }
    #pragma unroll
    for (int i = 0; i < 4; i++) {
        int gr = row0 + row_t + 16 * i;
        if (gr < N_NODES) {
            #pragma unroll
            for (int j = 0; j < 6; j++) {
                float v = fmaf(acc[i][j], sc[j], sh[j]);
                v = fmaxf(v, 0.f);
                out[(size_t)gr * H + c0 + j] = v;
                if (DUAL) out2[(size_t)gr * H + c0 + j] = v;
            }
        }
    }
}

// ---------------- pooling + head ----------------
__global__ void pool_kernel(const int* __restrict__ batch) {
    int t = blockIdx.x * blockDim.x + threadIdx.x;
    const int VPR = HID / 4; // 24
    int n = t / VPR;
    int lane = t - n * VPR;
    if (n >= N_NODES) return;
    int b = __ldg(&batch[n]);
    float4 v = *(const float4*)(g_h + (size_t)n * HID + lane * 4);
    red_add_v4(g_pool + (size_t)b * HID + lane * 4, v);
}

__global__ void head_kernel(const int* __restrict__ r_target,
                            const float* __restrict__ head_w,
                            const float* __restrict__ head_b,
                            float* __restrict__ out) {
    int b = threadIdx.x;
    if (b >= N_GRAPHS) return;
    int t = r_target[b];
    const float4* w = (const float4*)(head_w + (size_t)t * HID);
    const float4* p = (const float4*)(g_pool + (size_t)b * HID);
    float acc = 0.f;
    #pragma unroll
    for (int k = 0; k < HID / 4; k++) {
        float4 wv = w[k], pv = p[k];
        acc = fmaf(pv.x, wv.x, acc);
        acc = fmaf(pv.y, wv.y, acc);
        acc = fmaf(pv.z, wv.z, acc);
        acc = fmaf(pv.w, wv.w, acc);
    }
    out[b] = acc + head_b[t];
}

// ---------------- launch ----------------
extern "C" void kernel_launch(void* const* d_in, const int* in_sizes, int n_in,
                              void* d_out, int out_size) {
    const float* x    = (const float*)d_in[0];
    const int*   ei   = (const int*)d_in[1];
    const int*   bat  = (const int*)d_in[2];
    const int*   rtg  = (const int*)d_in[3];

    const float* w_in[3]  = {(const float*)d_in[4],  (const float*)d_in[12], (const float*)d_in[20]};
    const float* b_in[3]  = {(const float*)d_in[5],  (const float*)d_in[13], (const float*)d_in[21]};
    const float* gam[3]   = {(const float*)d_in[6],  (const float*)d_in[14], (const float*)d_in[22]};
    const float* bet[3]   = {(const float*)d_in[7],  (const float*)d_in[15], (const float*)d_in[23]};
    const float* rme[3]   = {(const float*)d_in[8],  (const float*)d_in[16], (const float*)d_in[24]};
    const float* rva[3]   = {(const float*)d_in[9],  (const float*)d_in[17], (const float*)d_in[25]};
    const float* w_out[3] = {(const float*)d_in[10], (const float*)d_in[18], (const float*)d_in[26]};
    const float* b_out[3] = {(const float*)d_in[11], (const float*)d_in[19], (const float*)d_in[27]};
    const float* head_w   = (const float*)d_in[28];
    const float* head_b   = (const float*)d_in[29];
    float* out = (float*)d_out;

    float *hbuf, *aggbuf, *zbuf;
    cudaGetSymbolAddress((void**)&hbuf, g_h);
    cudaGetSymbolAddress((void**)&aggbuf, g_agg);
    cudaGetSymbolAddress((void**)&zbuf, g_z);

    const int TB = 256;
    const int gemm_blocks = (N_NODES + 63) / 64;

    zero_pool_kernel<<<(N_GRAPHS * HID + TB - 1) / TB, TB>>>();

    // ---- layer 1 (Din=32) ----
    copy_x_kernel<<<(N_NODES * DIN0 / 4 + TB - 1) / TB, TB>>>(x);
    {
        int tot = N_EDGES * (DIN0 / 4);
        edge_kernel<DIN0><<<(tot + TB - 1) / TB, TB>>>(x, ei, aggbuf);
    }
    gemm_kernel<DIN0, true, false><<<gemm_blocks, TB>>>(
        aggbuf, w_in[0], b_in[0], gam[0], bet[0], rme[0], rva[0], zbuf, nullptr);
    gemm_kernel<HID, false, true><<<gemm_blocks, TB>>>(
        zbuf, w_out[0], b_out[0], nullptr, nullptr, nullptr, nullptr, hbuf, aggbuf);

    // ---- layer 2 ----
    {
        int tot = N_EDGES * (HID / 4);
        edge_kernel<HID><<<(tot + TB - 1) / TB, TB>>>(hbuf, ei, aggbuf);
    }
    gemm_kernel<HID, true, false><<<gemm_blocks, TB>>>(
        aggbuf, w_in[1], b_in[1], gam[1], bet[1], rme[1], rva[1], zbuf, nullptr);
    gemm_kernel<HID, false, true><<<gemm_blocks, TB>>>(
        zbuf, w_out[1], b_out[1], nullptr, nullptr, nullptr, nullptr, hbuf, aggbuf);

    // ---- layer 3 ----
    {
        int tot = N_EDGES * (HID / 4);
        edge_kernel<HID><<<(tot + TB - 1) / TB, TB>>>(hbuf, ei, aggbuf);
    }
    gemm_kernel<HID, true, false><<<gemm_blocks, TB>>>(
        aggbuf, w_in[2], b_in[2], gam[2], bet[2], rme[2], rva[2], zbuf, nullptr);
    gemm_kernel<HID, false, false><<<gemm_blocks, TB>>>(
        zbuf, w_out[2], b_out[2], nullptr, nullptr, nullptr, nullptr, hbuf, nullptr);

    // ---- pooling + head ----
    {
        int tot = N_NODES * (HID / 4);
        pool_kernel<<<(tot + TB - 1) / TB, TB>>>(bat);
    }
    head_kernel<<<1, 256>>>(rtg, head_w, head_b, out);
}

// round 5
// speedup vs baseline: 2.0419x; 1.2420x over previous
#include <cuda_runtime.h>
#include <cuda_bf16.h>
#include <stdint.h>

#define N_NODES 50000
#define N_EDGES 800000
#define N_GRAPHS 256
#define DIN0 32
#define HID 96
#define BN_EPS 1e-5f

// ---------------- device scratch (static, allowed) ----------------
__device__ float g_h[(size_t)N_NODES * HID];     // layer outputs
__device__ float g_agg[(size_t)N_NODES * HID];   // aggregation buffer (self + neighbors)
__device__ float g_z[(size_t)N_NODES * HID];     // intermediate z
__device__ float g_pool[N_GRAPHS * HID];         // pooled

// vectorized fire-and-forget global reduction (sm_90+)
__device__ __forceinline__ void red_add_v4(float* addr, float4 v) {
    asm volatile("red.global.add.v4.f32 [%0], {%1, %2, %3, %4};"
                 :: "l"(addr), "f"(v.x), "f"(v.y), "f"(v.z), "f"(v.w)
                 : "memory");
}

// ---------------- small kernels ----------------
__global__ void zero_pool_kernel() {
    int i = blockIdx.x * blockDim.x + threadIdx.x;
    if (i < N_GRAPHS * HID) g_pool[i] = 0.f;
}

__global__ void copy_x_kernel(const float* __restrict__ x) {
    int i = blockIdx.x * blockDim.x + threadIdx.x;
    int total = N_NODES * DIN0 / 4;
    if (i < total) {
        ((float4*)g_agg)[i] = ((const float4*)x)[i];
    }
}

// edge scatter: agg[dst] += h[src], one red.v4 per (edge, lane)
template<int DIN>
__global__ void edge_kernel(const float* __restrict__ h,
                            const int* __restrict__ ei,
                            float* __restrict__ agg) {
    const int VPR = DIN / 4;
    int t = blockIdx.x * blockDim.x + threadIdx.x;
    int e = t / VPR;
    int lane = t - e * VPR;
    if (e >= N_EDGES) return;
    int s = __ldg(&ei[e]);
    int d = __ldg(&ei[N_EDGES + e]);
    float4 v = *(const float4*)(h + (size_t)s * DIN + lane * 4);
    red_add_v4(agg + (size_t)d * DIN + lane * 4, v);
}

// ---------------- GEMM: out = epilogue(A[N x DIN] @ W[DIN x 96]) ----------------
// 192 threads = 16 row-threads x 12 col-threads; BM=64; microtile 4 rows x 8 cols.
// A k-tile stored TRANSPOSED in smem (As[kk][r]) -> a-fragment is one LDS.128.
// W smem-resident, 8-col fragment = 2x LDS.128. Double-buffered k-tiles.
template<int DIN, bool HAS_BN, bool DUAL>
__global__ void __launch_bounds__(192, 5) gemm_kernel(
    const float* __restrict__ A, const float* __restrict__ W,
    const float* __restrict__ bias,
    const float* __restrict__ gamma, const float* __restrict__ beta,
    const float* __restrict__ rmean, const float* __restrict__ rvar,
    float* __restrict__ out, float* __restrict__ out2)
{
    constexpr int H = HID;
    constexpr int BM = 64;
    constexpr int KT = 16;
    constexpr int NKT = DIN / KT;
    constexpr int NV = BM * (KT / 4);       // 256 float4 stage items per tile
    __shared__ float Ws[DIN * H];           // 12KB (DIN=32) / 36KB (DIN=96)
    __shared__ float As[2][KT][BM];         // 2 x 4KB

    const int tid = threadIdx.x;
    const int row0 = blockIdx.x * BM;

    for (int i = tid; i < DIN * H / 4; i += 192)
        ((float4*)Ws)[i] = ((const float4*)W)[i];

    const int row_t = tid & 15;         // 0..15
    const int col_t = tid >> 4;         // 0..11
    const int r0 = row_t * 4;           // 4 contiguous rows
    const int c0 = col_t * 8;           // 8 contiguous cols (f4-aligned)

    float acc[4][8];
    #pragma unroll
    for (int i = 0; i < 4; i++)
        #pragma unroll
        for (int j = 0; j < 8; j++) acc[i][j] = 0.f;

    float4 vst[2];

    // prologue: load + store tile kt=0 into buf 0
    #pragma unroll
    for (int it = 0; it < 2; it++) {
        int i = tid + it * 192;
        if (i < NV) {
            int r = i & 63, kv = i >> 6;
            int gr = row0 + r;
            vst[it] = (gr < N_NODES)
                ? *(const float4*)(A + (size_t)gr * DIN + kv * 4)
                : make_float4(0.f, 0.f, 0.f, 0.f);
        }
    }
    #pragma unroll
    for (int it = 0; it < 2; it++) {
        int i = tid + it * 192;
        if (i < NV) {
            int r = i & 63, kv = i >> 6;
            As[0][kv * 4 + 0][r] = vst[it].x;
            As[0][kv * 4 + 1][r] = vst[it].y;
            As[0][kv * 4 + 2][r] = vst[it].z;
            As[0][kv * 4 + 3][r] = vst[it].w;
        }
    }
    __syncthreads();

    int buf = 0;
    for (int kt = 0; kt < NKT; kt++) {
        // prefetch next tile into registers (overlaps with compute)
        if (kt + 1 < NKT) {
            #pragma unroll
            for (int it = 0; it < 2; it++) {
                int i = tid + it * 192;
                if (i < NV) {
                    int r = i & 63, kv = i >> 6;
                    int gr = row0 + r;
                    vst[it] = (gr < N_NODES)
                        ? *(const float4*)(A + (size_t)gr * DIN + (kt + 1) * KT + kv * 4)
                        : make_float4(0.f, 0.f, 0.f, 0.f);
                }
            }
        }

        #pragma unroll
        for (int kk = 0; kk < KT; kk++) {
            float4 a4 = *(const float4*)&As[buf][kk][r0];
            const float4* wr = (const float4*)&Ws[(kt * KT + kk) * H + c0];
            float4 w0 = wr[0], w1 = wr[1];
            float a[4] = {a4.x, a4.y, a4.z, a4.w};
            float w[8] = {w0.x, w0.y, w0.z, w0.w, w1.x, w1.y, w1.z, w1.w};
            #pragma unroll
            for (int i = 0; i < 4; i++)
                #pragma unroll
                for (int j = 0; j < 8; j++)
                    acc[i][j] = fmaf(a[i], w[j], acc[i][j]);
        }

        if (kt + 1 < NKT) {
            #pragma unroll
            for (int it = 0; it < 2; it++) {
                int i = tid + it * 192;
                if (i < NV) {
                    int r = i & 63, kv = i >> 6;
                    As[buf ^ 1][kv * 4 + 0][r] = vst[it].x;
                    As[buf ^ 1][kv * 4 + 1][r] = vst[it].y;
                    As[buf ^ 1][kv * 4 + 2][r] = vst[it].z;
                    As[buf ^ 1][kv * 4 + 3][r] = vst[it].w;
                }
            }
            __syncthreads();
        }
        buf ^= 1;
    }

    // epilogue: (+bias), optional BN, relu, vectorized stores
    float sc[8], sh[8];
    #pragma unroll
    for (int j = 0; j < 8; j++) {
        int c = c0 + j;
        if (HAS_BN) {
            float s = gamma[c] * rsqrtf(rvar[c] + BN_EPS);
            sc[j] = s;
            sh[j] = (bias[c] - rmean[c]) * s + beta[c];
        } else {
            sc[j] = 1.f;
            sh[j] = bias[c];
        }
    }
    #pragma unroll
    for (int i = 0; i < 4; i++) {
        int gr = row0 + r0 + i;
        if (gr < N_NODES) {
            float v[8];
            #pragma unroll
            for (int j = 0; j < 8; j++)
                v[j] = fmaxf(fmaf(acc[i][j], sc[j], sh[j]), 0.f);
            float4 o0 = make_float4(v[0], v[1], v[2], v[3]);
            float4 o1 = make_float4(v[4], v[5], v[6], v[7]);
            *(float4*)(out + (size_t)gr * H + c0) = o0;
            *(float4*)(out + (size_t)gr * H + c0 + 4) = o1;
            if (DUAL) {
                *(float4*)(out2 + (size_t)gr * H + c0) = o0;
                *(float4*)(out2 + (size_t)gr * H + c0 + 4) = o1;
            }
        }
    }
}

// ---------------- pooling + head ----------------
__global__ void pool_kernel(const int* __restrict__ batch) {
    int t = blockIdx.x * blockDim.x + threadIdx.x;
    const int VPR = HID / 4; // 24
    int n = t / VPR;
    int lane = t - n * VPR;
    if (n >= N_NODES) return;
    int b = __ldg(&batch[n]);
    float4 v = *(const float4*)(g_h + (size_t)n * HID + lane * 4);
    red_add_v4(g_pool + (size_t)b * HID + lane * 4, v);
}

__global__ void head_kernel(const int* __restrict__ r_target,
                            const float* __restrict__ head_w,
                            const float* __restrict__ head_b,
                            float* __restrict__ out) {
    int b = threadIdx.x;
    if (b >= N_GRAPHS) return;
    int t = r_target[b];
    const float4* w = (const float4*)(head_w + (size_t)t * HID);
    const float4* p = (const float4*)(g_pool + (size_t)b * HID);
    float acc = 0.f;
    #pragma unroll
    for (int k = 0; k < HID / 4; k++) {
        float4 wv = w[k], pv = p[k];
        acc = fmaf(pv.x, wv.x, acc);
        acc = fmaf(pv.y, wv.y, acc);
        acc = fmaf(pv.z, wv.z, acc);
        acc = fmaf(pv.w, wv.w, acc);
    }
    out[b] = acc + head_b[t];
}

// ---------------- launch ----------------
extern "C" void kernel_launch(void* const* d_in, const int* in_sizes, int n_in,
                              void* d_out, int out_size) {
    const float* x    = (const float*)d_in[0];
    const int*   ei   = (const int*)d_in[1];
    const int*   bat  = (const int*)d_in[2];
    const int*   rtg  = (const int*)d_in[3];

    const float* w_in[3]  = {(const float*)d_in[4],  (const float*)d_in[12], (const float*)d_in[20]};
    const float* b_in[3]  = {(const float*)d_in[5],  (const float*)d_in[13], (const float*)d_in[21]};
    const float* gam[3]   = {(const float*)d_in[6],  (const float*)d_in[14], (const float*)d_in[22]};
    const float* bet[3]   = {(const float*)d_in[7],  (const float*)d_in[15], (const float*)d_in[23]};
    const float* rme[3]   = {(const float*)d_in[8],  (const float*)d_in[16], (const float*)d_in[24]};
    const float* rva[3]   = {(const float*)d_in[9],  (const float*)d_in[17], (const float*)d_in[25]};
    const float* w_out[3] = {(const float*)d_in[10], (const float*)d_in[18], (const float*)d_in[26]};
    const float* b_out[3] = {(const float*)d_in[11], (const float*)d_in[19], (const float*)d_in[27]};
    const float* head_w   = (const float*)d_in[28];
    const float* head_b   = (const float*)d_in[29];
    float* out = (float*)d_out;

    float *hbuf, *aggbuf, *zbuf;
    cudaGetSymbolAddress((void**)&hbuf, g_h);
    cudaGetSymbolAddress((void**)&aggbuf, g_agg);
    cudaGetSymbolAddress((void**)&zbuf, g_z);

    const int TB = 256;
    const int GB = 192;                         // gemm block size
    const int gemm_blocks = (N_NODES + 63) / 64;

    zero_pool_kernel<<<(N_GRAPHS * HID + TB - 1) / TB, TB>>>();

    // ---- layer 1 (Din=32) ----
    copy_x_kernel<<<(N_NODES * DIN0 / 4 + TB - 1) / TB, TB>>>(x);
    {
        int tot = N_EDGES * (DIN0 / 4);
        edge_kernel<DIN0><<<(tot + TB - 1) / TB, TB>>>(x, ei, aggbuf);
    }
    gemm_kernel<DIN0, true, false><<<gemm_blocks, GB>>>(
        aggbuf, w_in[0], b_in[0], gam[0], bet[0], rme[0], rva[0], zbuf, nullptr);
    gemm_kernel<HID, false, true><<<gemm_blocks, GB>>>(
        zbuf, w_out[0], b_out[0], nullptr, nullptr, nullptr, nullptr, hbuf, aggbuf);

    // ---- layer 2 ----
    {
        int tot = N_EDGES * (HID / 4);
        edge_kernel<HID><<<(tot + TB - 1) / TB, TB>>>(hbuf, ei, aggbuf);
    }
    gemm_kernel<HID, true, false><<<gemm_blocks, GB>>>(
        aggbuf, w_in[1], b_in[1], gam[1], bet[1], rme[1], rva[1], zbuf, nullptr);
    gemm_kernel<HID, false, true><<<gemm_blocks, GB>>>(
        zbuf, w_out[1], b_out[1], nullptr, nullptr, nullptr, nullptr, hbuf, aggbuf);

    // ---- layer 3 ----
    {
        int tot = N_EDGES * (HID / 4);
        edge_kernel<HID><<<(tot + TB - 1) / TB, TB>>>(hbuf, ei, aggbuf);
    }
    gemm_kernel<HID, true, false><<<gemm_blocks, GB>>>(
        aggbuf, w_in[2], b_in[2], gam[2], bet[2], rme[2], rva[2], zbuf, nullptr);
    gemm_kernel<HID, false, false><<<gemm_blocks, GB>>>(
        zbuf, w_out[2], b_out[2], nullptr, nullptr, nullptr, nullptr, hbuf, nullptr);

    // ---- pooling + head ----
    {
        int tot = N_NODES * (HID / 4);
        pool_kernel<<<(tot + TB - 1) / TB, TB>>>(bat);
    }
    head_kernel<<<1, 256>>>(rtg, head_w, head_b, out);
}